// round 17
// baseline (speedup 1.0000x reference)
#include <cuda_runtime.h>

// SSIM map: 3x3 mean (reflect pad 1), fp32. cp.async smem row-ring, 2 rows
// per pipeline step, NO __syncthreads: each thread reads only its own smem
// region (per-thread wait_group ordering), column halo via warp shuffle,
// warp-edge halo via __ldg (L1-hit: cp.async.ca populated the line).
// Shapes fixed: planes=96, H=384, W=640.

#define HH 384
#define WW 640
#define CHUNK 32           // output rows per block
#define NSTEP (CHUNK / 2)  // 16 pipeline steps (2 rows each)
#define RING 8             // smem ring slots (rows)
#define TPB 160            // 160 threads * 4 cols = 640

__device__ __forceinline__ int rrow(int r) {
    return r < 0 ? -r : (r >= HH ? 2 * HH - 2 - r : r);
}

__device__ __forceinline__ void cp16(float* s, const float* g) {
    unsigned sa = (unsigned)__cvta_generic_to_shared(s);
    asm volatile("cp.async.ca.shared.global [%0], [%1], 16;" :: "r"(sa), "l"(g));
}
__device__ __forceinline__ void cp_commit() {
    asm volatile("cp.async.commit_group;");
}
__device__ __forceinline__ void cp_wait1() {
    asm volatile("cp.async.wait_group 1;");
}

__global__ __launch_bounds__(TPB)
void ssim_kernel(const float* __restrict__ x,
                 const float* __restrict__ y,
                 float* __restrict__ out)
{
    __shared__ float xs[RING][WW];
    __shared__ float ys[RING][WW];

    const int tid   = threadIdx.x;
    const int lane  = tid & 31;
    const int c0    = tid * 4;
    const int plane = blockIdx.y;
    const int r0    = blockIdx.x * CHUNK;

    const size_t pbase = (size_t)plane * HH * WW;
    const float* xp = x + pbase;
    const float* yp = y + pbase;
    float* op       = out + pbase;

    // Halo classification (per thread, loop-invariant).
    const bool lm    = (lane == 0);          // needs left halo from outside warp
    const bool rm    = (lane == 31);         // needs right halo from outside warp
    const bool ledge = (c0 == 0);            // image left border: reflect -> own v.y
    const bool redge = (c0 + 4 >= WW);       // image right border: reflect -> own v.z

    const float C1S = 81.0f * 1.0e-4f;   // 81*C1 (x81^2 rescale cancels)
    const float C2S = 81.0f * 9.0e-4f;   // 81*C2

    // Pull one row (ring slot ss, input row index k) into a 6-col register row.
    // Bulk from own smem region; halo via shfl / __ldg / own-register reflect.
    #define PULL_ROW(dstx, dsty, ss, kk)                                          \
    {                                                                              \
        const int rg = rrow(r0 - 1 + (kk));                                        \
        float4 v = *(const float4*)(&xs[(ss)][c0]);                                \
        float4 w = *(const float4*)(&ys[(ss)][c0]);                                \
        float xm1 = __shfl_up_sync(0xFFFFFFFFu, v.w, 1);                           \
        float xp4 = __shfl_down_sync(0xFFFFFFFFu, v.x, 1);                         \
        float ym1 = __shfl_up_sync(0xFFFFFFFFu, w.w, 1);                           \
        float yp4 = __shfl_down_sync(0xFFFFFFFFu, w.x, 1);                         \
        if (lm) {                                                                  \
            if (ledge) { xm1 = v.y; ym1 = w.y; }                                   \
            else {                                                                 \
                xm1 = __ldg(xp + (size_t)rg * WW + c0 - 1);                        \
                ym1 = __ldg(yp + (size_t)rg * WW + c0 - 1);                        \
            }                                                                      \
        }                                                                          \
        if (rm) {                                                                  \
            if (redge) { xp4 = v.z; yp4 = w.z; }                                   \
            else {                                                                 \
                xp4 = __ldg(xp + (size_t)rg * WW + c0 + 4);                        \
                yp4 = __ldg(yp + (size_t)rg * WW + c0 + 4);                        \
            }                                                                      \
        }                                                                          \
        dstx[0] = xm1; dstx[1] = v.x; dstx[2] = v.y;                               \
        dstx[3] = v.z; dstx[4] = v.w; dstx[5] = xp4;                               \
        dsty[0] = ym1; dsty[1] = w.x; dsty[2] = w.y;                               \
        dsty[3] = w.z; dsty[4] = w.w; dsty[5] = yp4;                               \
    }

    // ---- Prologue: issue groups g=0..2 (rows k=2g, 2g+1; slot=k) ----
    #pragma unroll
    for (int g = 0; g < 3; g++) {
        #pragma unroll
        for (int rr = 0; rr < 2; rr++) {
            const int k = 2 * g + rr;
            const int r = rrow(r0 - 1 + k);
            cp16(&xs[k][c0], xp + (size_t)r * WW + c0);
            cp16(&ys[k][c0], yp + (size_t)r * WW + c0);
        }
        cp_commit();
    }
    cp_wait1();              // groups 0,1 done -> rows k=0..3 in own smem region

    // 4-row register rotation, reg slot = k % 4. Seed rows k=0,1.
    float xr[4][6], yr[4][6];
    PULL_ROW(xr[0], yr[0], 0, 0);
    PULL_ROW(xr[1], yr[1], 1, 1);

    // ---- Main: NSTEP steps, 4-step unroll keeps every slot index static ----
    #pragma unroll 1
    for (int tt = 0; tt < NSTEP; tt += 4) {
        #pragma unroll
        for (int u = 0; u < 4; u++) {
            const int t = tt + u;

            // Wait: groups <= t+1 complete (rows k <= 2t+3 in own region).
            cp_wait1();

            // Issue group t+3 (rows k=2t+6, 2t+7 -> slots (2u+6)%8,(2u+7)%8).
            // Guarded tail; ALWAYS commit to keep group counts aligned.
            {
                const int k0 = 2 * t + 6, k1 = 2 * t + 7;
                if (k0 <= CHUNK + 1) {
                    const int r = rrow(r0 - 1 + k0);
                    cp16(&xs[(2 * u + 6) % RING][c0], xp + (size_t)r * WW + c0);
                    cp16(&ys[(2 * u + 6) % RING][c0], yp + (size_t)r * WW + c0);
                }
                if (k1 <= CHUNK + 1) {
                    const int r = rrow(r0 - 1 + k1);
                    cp16(&xs[(2 * u + 7) % RING][c0], xp + (size_t)r * WW + c0);
                    cp16(&ys[(2 * u + 7) % RING][c0], yp + (size_t)r * WW + c0);
                }
                cp_commit();
            }

            // Pull rows k=2t+2, 2t+3 into the register rotation.
            PULL_ROW(xr[(2 * u + 2) % 4], yr[(2 * u + 2) % 4],
                     (2 * u + 2) % RING, 2 * t + 2);
            PULL_ROW(xr[(2 * u + 3) % 4], yr[(2 * u + 3) % 4],
                     (2 * u + 3) % RING, 2 * t + 3);

            // Register slots for input rows A=2t, B=2t+1, C=2t+2, D=2t+3.
            const int sA = (2 * u) % 4,     sB = (2 * u + 1) % 4;
            const int sC = (2 * u + 2) % 4, sD = (2 * u + 3) % 4;

            // ---- Pair-shared vertical sums (output rows 2t and 2t+1) ----
            float sx0[6], sy0[6], sxx0[6], syy0[6], sxy0[6];
            float sx1[6], sy1[6], sxx1[6], syy1[6], sxy1[6];
            #pragma unroll
            for (int j = 0; j < 6; j++) {
                const float aA = xr[sA][j], aB = xr[sB][j], aC = xr[sC][j], aD = xr[sD][j];
                const float bA = yr[sA][j], bB = yr[sB][j], bC = yr[sC][j], bD = yr[sD][j];
                const float mx  = aB + aC;
                const float my  = bB + bC;
                const float mxx = fmaf(aB, aB, aC * aC);
                const float myy = fmaf(bB, bB, bC * bC);
                const float mxy = fmaf(aB, bB, aC * bC);
                sx0[j]  = aA + mx;              sx1[j]  = mx + aD;
                sy0[j]  = bA + my;              sy1[j]  = my + bD;
                sxx0[j] = fmaf(aA, aA, mxx);    sxx1[j] = fmaf(aD, aD, mxx);
                syy0[j] = fmaf(bA, bA, myy);    syy1[j] = fmaf(bD, bD, myy);
                sxy0[j] = fmaf(aA, bA, mxy);    sxy1[j] = fmaf(aD, bD, mxy);
            }

            // ---- Horizontal sums + epilogue, per output row ----
            #define ROW_OUT(sx, sy, sxx, syy, sxy, ROWI)                              \
            {                                                                          \
                float Sx[4], Sy[4], Sxx[4], Syy[4], Sxy[4];                            \
                {                                                                      \
                    float u1, v1;                                                      \
                    u1 = sx[1] + sx[2];   v1 = sx[3] + sx[4];                          \
                    Sx[0] = sx[0] + u1;  Sx[1] = u1 + sx[3];                           \
                    Sx[2] = sx[2] + v1;  Sx[3] = v1 + sx[5];                           \
                    u1 = sy[1] + sy[2];   v1 = sy[3] + sy[4];                          \
                    Sy[0] = sy[0] + u1;  Sy[1] = u1 + sy[3];                           \
                    Sy[2] = sy[2] + v1;  Sy[3] = v1 + sy[5];                           \
                    u1 = sxx[1] + sxx[2]; v1 = sxx[3] + sxx[4];                        \
                    Sxx[0] = sxx[0] + u1; Sxx[1] = u1 + sxx[3];                        \
                    Sxx[2] = sxx[2] + v1; Sxx[3] = v1 + sxx[5];                        \
                    u1 = syy[1] + syy[2]; v1 = syy[3] + syy[4];                        \
                    Syy[0] = syy[0] + u1; Syy[1] = u1 + syy[3];                        \
                    Syy[2] = syy[2] + v1; Syy[3] = v1 + syy[5];                        \
                    u1 = sxy[1] + sxy[2]; v1 = sxy[3] + sxy[4];                        \
                    Sxy[0] = sxy[0] + u1; Sxy[1] = u1 + sxy[3];                        \
                    Sxy[2] = sxy[2] + v1; Sxy[3] = v1 + sxy[5];                        \
                }                                                                      \
                float resv[4];                                                         \
                _Pragma("unroll")                                                      \
                for (int o = 0; o < 4; o++) {                                          \
                    const float P  = Sx[o] * Sy[o];                                    \
                    const float Qx = Sx[o] * Sx[o];                                    \
                    const float Qy = Sy[o] * Sy[o];                                    \
                    const float A  = fmaf(Sxx[o], 9.0f, -Qx);                          \
                    const float B  = fmaf(Syy[o], 9.0f, -Qy);                          \
                    const float Cc = fmaf(Sxy[o], 9.0f, -P);                           \
                    const float num = fmaf(P, 2.0f, C1S) * fmaf(Cc, 2.0f, C2S);        \
                    const float den = (Qx + Qy + C1S) * (A + B + C2S);                 \
                    float s = __fdividef(num, den);                                    \
                    resv[o] = fminf(fmaxf(s, 0.0f), 1.0f);                             \
                }                                                                      \
                __stcs((float4*)(op + (size_t)(r0 + (ROWI)) * WW + c0),                \
                       make_float4(resv[0], resv[1], resv[2], resv[3]));               \
            }

            ROW_OUT(sx0, sy0, sxx0, syy0, sxy0, 2 * t);
            ROW_OUT(sx1, sy1, sxx1, syy1, sxy1, 2 * t + 1);
            #undef ROW_OUT
        }
    }
    #undef PULL_ROW
}

extern "C" void kernel_launch(void* const* d_in, const int* in_sizes, int n_in,
                              void* d_out, int out_size) {
    const float* x = (const float*)d_in[0];
    const float* y = (const float*)d_in[1];
    float* out = (float*)d_out;

    const int planes = in_sizes[0] / (HH * WW);   // 96
    dim3 grid(HH / CHUNK, planes);                // (12, 96)
    ssim_kernel<<<grid, TPB>>>(x, y, out);
}